// round 8
// baseline (speedup 1.0000x reference)
#include <cuda_runtime.h>
#include <math.h>

#define Bsz 8192
#define Dd  1024
#define Rr  64
#define TB  16
#define NT  512

typedef unsigned long long ull;

// ---- Yoshida 4th-order coefficients ----
constexpr double kCbrt2 = 1.2599210498948731647672106072782;
constexpr double kW1 = 1.0 / (2.0 - kCbrt2);
constexpr double kW0 = -kCbrt2 * kW1;
constexpr double kDT = 0.01;

#define C1DT  ((float)((kW1 * 0.5) * kDT))
#define C2DT  ((float)(((kW0 + kW1) * 0.5) * kDT))
#define C4DT  C1DT
#define C41DT ((float)(kW1 * kDT))          // (C4 + C1) * dt
#define D1DT  ((float)(kW1 * kDT))
#define D2DT  ((float)(kW0 * kDT))

#define PLASTICITY    0.1f
#define SING_THRESH   10.0f
#define SING_STRENGTH 20.0f

// ---- packed f32x2 helpers (Blackwell) ----
__device__ __forceinline__ ull splat2(float x) {
    ull r; asm("mov.b64 %0, {%1, %1};" : "=l"(r) : "f"(x)); return r;
}
__device__ __forceinline__ ull fma2(ull a, ull b, ull c) {
    ull d; asm("fma.rn.f32x2 %0, %1, %2, %3;" : "=l"(d) : "l"(a), "l"(b), "l"(c)); return d;
}
__device__ __forceinline__ ull add2(ull a, ull b) {
    ull d; asm("add.rn.f32x2 %0, %1, %2;" : "=l"(d) : "l"(a), "l"(b)); return d;
}
__device__ __forceinline__ float2 unpk2(ull v) {
    float2 r; asm("mov.b64 {%0, %1}, %2;" : "=f"(r.x), "=f"(r.y) : "l"(v)); return r;
}

// Process one 4-d block: 8 rows x 4 r's, in two 4-row halves to limit registers.
__device__ __forceinline__ void block_fma(const float* __restrict__ sb, int d,
                                          const ulonglong2* u, ull* A)
{
    #pragma unroll
    for (int half = 0; half < 2; ++half) {
        float4 sv[4];
        #pragma unroll
        for (int j = 0; j < 4; ++j)
            sv[j] = *(const float4*)(sb + (half * 4 + j) * Dd + d);
        ull* Ah = A + half * 8;
        #pragma unroll
        for (int dd = 0; dd < 4; ++dd) {
            #pragma unroll
            for (int j = 0; j < 4; ++j) {
                const float f = (dd == 0) ? sv[j].x : (dd == 1) ? sv[j].y
                              : (dd == 2) ? sv[j].z : sv[j].w;
                const ull sp = splat2(f);
                Ah[j * 2 + 0] = fma2(sp, u[dd].x, Ah[j * 2 + 0]);
                Ah[j * 2 + 1] = fma2(sp, u[dd].y, Ah[j * 2 + 1]);
            }
        }
    }
}

// Rank pass with software-pipelined matrix LDG (one 4-d block ahead).
__device__ __forceinline__ void rank_pass(const float* __restrict__ st,
                                          const float* __restrict__ mat,
                                          int rq, int w8, int d0, ull* A)
{
    #pragma unroll
    for (int c = 0; c < 16; ++c) A[c] = 0ull;
    const float* sb = st + (size_t)w8 * Dd + d0;
    const float* mb = mat + (size_t)d0 * Rr + rq;

    ulonglong2 u[4];
    #pragma unroll
    for (int dd = 0; dd < 4; ++dd)
        u[dd] = *(const ulonglong2*)(mb + (size_t)dd * Rr);

    #pragma unroll 1
    for (int d = 0; d < 60; d += 4) {
        ulonglong2 un[4];
        #pragma unroll
        for (int dd = 0; dd < 4; ++dd)
            un[dd] = *(const ulonglong2*)(mb + (size_t)(d + 4 + dd) * Rr);
        block_fma(sb, d, u, A);
        #pragma unroll
        for (int dd = 0; dd < 4; ++dd) u[dd] = un[dd];
    }
    block_fma(sb, 60, u, A);
}

__global__ void __launch_bounds__(NT, 1)
yoshida_kernel(const float* __restrict__ x_in,
               const float* __restrict__ v_in,
               const float* __restrict__ force,
               const float* __restrict__ U,     // [D, R]
               const float* __restrict__ Wm,    // [R, D]
               const float* __restrict__ Vw,    // [D, R]
               const int*   __restrict__ steps_p,
               float* __restrict__ out)         // [x(B*D) ; v(B*D)]
{
    extern __shared__ float smem[];
    float* xs     = smem;                       // 16384 floats
    float* vs     = xs + TB * Dd;               // 16384
    float* qs     = vs + TB * Dd;               // 1024  (qs[r*TB + row], sing folded)
    float* sing_s = qs + Rr * TB;               // 16
    ull*   partP  = (ull*)(sing_s + TB);        // 4096 ull = 32KB
    ull*   partM  = partP + 4096;               // 4096 ull = 32KB

    const int tid  = threadIdx.x;
    const int row0 = blockIdx.x * TB;

    float4* sx4 = (float4*)xs;
    float4* sv4 = (float4*)vs;

    // ---- phase-2 mapping: 16 r-quads x (2 ds-parity in-warp) x 2 row-octets x 8 ds-hi ----
    const int rqi = tid & 15;
    const int rq  = rqi * 4;
    const int dsl = (tid >> 4) & 1;
    const int w8a = ((tid >> 5) & 1) * 8;
    const int dsh = tid >> 6;                   // 0..7
    const int d0  = (dsh * 2 + dsl) * 64;
    const int grp = rqi + ((tid >> 5) & 1) * 16;   // 0..31
    // ---- reduce mapping: 16 components x 32 groups ----
    const int rc  = tid >> 5;                   // component 0..15
    const int rg  = tid & 31;                   // group 0..31
    // ---- phase-3 mapping: 256 k-quads x 2 row-octets ----
    const int k4  = (tid & 255) * 4;
    const int w8b = (tid >> 8) * 8;
    // ---- drift mapping: warp per row ----
    const int drow = tid >> 5;
    const int lane = tid & 31;

    // ---- load state tile ----
    {
        const float4* gx = (const float4*)(x_in + (size_t)row0 * Dd);
        const float4* gv = (const float4*)(v_in + (size_t)row0 * Dd);
        #pragma unroll
        for (int i = tid; i < TB * Dd / 4; i += NT) {
            sx4[i] = gx[i];
            sv4[i] = gv[i];
        }
    }

    const int nkicks = 3 * (*steps_p);

    for (int k = 0; k < nkicks; ++k) {
        const int sub = k - (k / 3) * 3;
        const float cdt = (k == 0) ? C1DT : (sub == 0) ? C41DT : C2DT;
        const float ddt = (sub == 1) ? D2DT : D1DT;

        __syncthreads();   // vs from prev kick visible

        ull A[16];

        // ---- P-pass: P = v.U (pre-kick v; independent of drift) ----
        rank_pass(vs, U, rq, w8a, d0, A);
        #pragma unroll
        for (int c = 0; c < 16; ++c)
            A[c] = add2(A[c], __shfl_xor_sync(0xffffffffu, A[c], 16));
        if (dsl == 0) {
            #pragma unroll
            for (int c = 0; c < 16; ++c)
                partP[c * 256 + dsh * 32 + grp] = A[c];
        }

        // ---- drift + sing fused (warp per row, packed FMA2) ----
        {
            ulonglong2* xr = (ulonglong2*)(xs + drow * Dd);
            const ulonglong2* vr = (const ulonglong2*)(vs + drow * Dd);
            const ull cd2 = splat2(cdt);
            ull acc2 = 0ull;
            #pragma unroll
            for (int i = 0; i < 8; ++i) {
                ulonglong2 xv = xr[lane + 32 * i];
                const ulonglong2 vv = vr[lane + 32 * i];
                xv.x = fma2(cd2, vv.x, xv.x);
                xv.y = fma2(cd2, vv.y, xv.y);
                acc2 = fma2(xv.x, xv.x, acc2);
                acc2 = fma2(xv.y, xv.y, acc2);
                xr[lane + 32 * i] = xv;
            }
            const float2 a2 = unpk2(acc2);
            float acc = a2.x + a2.y;
            #pragma unroll
            for (int o = 16; o; o >>= 1)
                acc += __shfl_xor_sync(0xffffffffu, acc, o);
            if (lane == 0)
                sing_s[drow] = 1.0f + SING_STRENGTH * expf(-acc * (1.0f / SING_THRESH));
        }
        __syncthreads();   // drifted x visible for M-pass

        // ---- M-pass: M = x.Vw (drifted x) ----
        rank_pass(xs, Vw, rq, w8a, d0, A);
        #pragma unroll
        for (int c = 0; c < 16; ++c)
            A[c] = add2(A[c], __shfl_xor_sync(0xffffffffu, A[c], 16));
        if (dsl == 0) {
            #pragma unroll
            for (int c = 0; c < 16; ++c)
                partM[c * 256 + dsh * 32 + grp] = A[c];
        }
        __syncthreads();   // both partial sets visible

        // ---- force prefetch for phase 3 (hides L2 latency under reduce) ----
        float4 fpre[8];
        #pragma unroll
        for (int j = 0; j < 8; ++j)
            fpre[j] = *(const float4*)(force + (size_t)(row0 + w8b + j) * Dd + k4);

        // ---- combined reduce (P and M) + q epilogue (sing folded) ----
        {
            ull accP = partP[rc * 256 + rg];
            ull accM = partM[rc * 256 + rg];
            #pragma unroll
            for (int p = 1; p < 8; ++p) {
                accP = add2(accP, partP[rc * 256 + p * 32 + rg]);
                accM = add2(accM, partM[rc * 256 + p * 32 + rg]);
            }
            const float2 pv = unpk2(accP);
            const float2 m  = unpk2(accM);
            const int rowq = (rg >> 4) * 8 + (rc >> 1);
            const int rr   = (rg & 15) * 4 + (rc & 1) * 2;
            const float sg = sing_s[rowq];
            qs[(rr + 0) * TB + rowq] = pv.x * pv.x * (1.0f + PLASTICITY * tanhf(m.x)) * sg;
            qs[(rr + 1) * TB + rowq] = pv.y * pv.y * (1.0f + PLASTICITY * tanhf(m.y)) * sg;
        }
        __syncthreads();

        // ---- phase 3: gamma = q.W (FMA2 over row-pairs, W prefetched);
        //      v += ddt*(force - gamma) ----
        {
            ull Acc[16];   // Acc[k*4 + rowpair]
            #pragma unroll
            for (int c = 0; c < 16; ++c) Acc[c] = 0ull;

            float4 w0 = *(const float4*)(Wm + k4);
            float4 w1 = *(const float4*)(Wm + Dd + k4);

            #pragma unroll 1
            for (int r = 0; r < Rr; r += 2) {
                float4 w0n, w1n;
                if (r < Rr - 2) {
                    w0n = *(const float4*)(Wm + (size_t)(r + 2) * Dd + k4);
                    w1n = *(const float4*)(Wm + (size_t)(r + 3) * Dd + k4);
                }
                const ulonglong2 qa0 = *(const ulonglong2*)(qs + r * TB + w8b);
                const ulonglong2 qb0 = *(const ulonglong2*)(qs + r * TB + w8b + 4);
                const ulonglong2 qa1 = *(const ulonglong2*)(qs + (r + 1) * TB + w8b);
                const ulonglong2 qb1 = *(const ulonglong2*)(qs + (r + 1) * TB + w8b + 4);
                {
                    const ull s0 = splat2(w0.x), s1 = splat2(w0.y);
                    const ull s2 = splat2(w0.z), s3 = splat2(w0.w);
                    Acc[0]  = fma2(qa0.x, s0, Acc[0]);  Acc[1]  = fma2(qa0.y, s0, Acc[1]);
                    Acc[2]  = fma2(qb0.x, s0, Acc[2]);  Acc[3]  = fma2(qb0.y, s0, Acc[3]);
                    Acc[4]  = fma2(qa0.x, s1, Acc[4]);  Acc[5]  = fma2(qa0.y, s1, Acc[5]);
                    Acc[6]  = fma2(qb0.x, s1, Acc[6]);  Acc[7]  = fma2(qb0.y, s1, Acc[7]);
                    Acc[8]  = fma2(qa0.x, s2, Acc[8]);  Acc[9]  = fma2(qa0.y, s2, Acc[9]);
                    Acc[10] = fma2(qb0.x, s2, Acc[10]); Acc[11] = fma2(qb0.y, s2, Acc[11]);
                    Acc[12] = fma2(qa0.x, s3, Acc[12]); Acc[13] = fma2(qa0.y, s3, Acc[13]);
                    Acc[14] = fma2(qb0.x, s3, Acc[14]); Acc[15] = fma2(qb0.y, s3, Acc[15]);
                }
                {
                    const ull s0 = splat2(w1.x), s1 = splat2(w1.y);
                    const ull s2 = splat2(w1.z), s3 = splat2(w1.w);
                    Acc[0]  = fma2(qa1.x, s0, Acc[0]);  Acc[1]  = fma2(qa1.y, s0, Acc[1]);
                    Acc[2]  = fma2(qb1.x, s0, Acc[2]);  Acc[3]  = fma2(qb1.y, s0, Acc[3]);
                    Acc[4]  = fma2(qa1.x, s1, Acc[4]);  Acc[5]  = fma2(qa1.y, s1, Acc[5]);
                    Acc[6]  = fma2(qb1.x, s1, Acc[6]);  Acc[7]  = fma2(qb1.y, s1, Acc[7]);
                    Acc[8]  = fma2(qa1.x, s2, Acc[8]);  Acc[9]  = fma2(qa1.y, s2, Acc[9]);
                    Acc[10] = fma2(qb1.x, s2, Acc[10]); Acc[11] = fma2(qb1.y, s2, Acc[11]);
                    Acc[12] = fma2(qa1.x, s3, Acc[12]); Acc[13] = fma2(qa1.y, s3, Acc[13]);
                    Acc[14] = fma2(qb1.x, s3, Acc[14]); Acc[15] = fma2(qb1.y, s3, Acc[15]);
                }
                w0 = w0n; w1 = w1n;
            }

            #pragma unroll
            for (int p = 0; p < 4; ++p) {
                const float2 g0 = unpk2(Acc[0 * 4 + p]);
                const float2 g1 = unpk2(Acc[1 * 4 + p]);
                const float2 g2 = unpk2(Acc[2 * 4 + p]);
                const float2 g3 = unpk2(Acc[3 * 4 + p]);
                const int re = w8b + 2 * p;
                {
                    const float4 f = fpre[2 * p];
                    float4* vp = (float4*)(vs + re * Dd + k4);
                    float4 vv = *vp;
                    vv.x += ddt * (f.x - g0.x);
                    vv.y += ddt * (f.y - g1.x);
                    vv.z += ddt * (f.z - g2.x);
                    vv.w += ddt * (f.w - g3.x);
                    *vp = vv;
                }
                {
                    const int ro = re + 1;
                    const float4 f = fpre[2 * p + 1];
                    float4* vp = (float4*)(vs + ro * Dd + k4);
                    float4 vv = *vp;
                    vv.x += ddt * (f.x - g0.y);
                    vv.y += ddt * (f.y - g1.y);
                    vv.z += ddt * (f.z - g2.y);
                    vv.w += ddt * (f.w - g3.y);
                    *vp = vv;
                }
            }
        }
    }

    // ---- store: out.x = xs + C4*dt*vs (final drift fused), out.v = vs ----
    __syncthreads();
    {
        const float fc = (nkicks > 0) ? C4DT : 0.0f;
        float4* ox = (float4*)(out + (size_t)row0 * Dd);
        float4* ov = (float4*)(out + (size_t)Bsz * Dd + (size_t)row0 * Dd);
        #pragma unroll
        for (int i = tid; i < TB * Dd / 4; i += NT) {
            const float4 xv = sx4[i];
            const float4 vv = sv4[i];
            float4 o;
            o.x = xv.x + fc * vv.x; o.y = xv.y + fc * vv.y;
            o.z = xv.z + fc * vv.z; o.w = xv.w + fc * vv.w;
            ox[i] = o;
            ov[i] = vv;
        }
    }
}

extern "C" void kernel_launch(void* const* d_in, const int* in_sizes, int n_in,
                              void* d_out, int out_size) {
    const float* x     = (const float*)d_in[0];
    const float* v     = (const float*)d_in[1];
    const float* force = (const float*)d_in[2];
    const float* U     = (const float*)d_in[3];
    const float* W     = (const float*)d_in[4];
    const float* Vw    = (const float*)d_in[5];
    const int*   steps = (const int*)d_in[6];

    const size_t smem = (size_t)(2 * TB * Dd + Rr * TB + TB) * sizeof(float)
                      + (size_t)(2 * 4096) * sizeof(ull);
    cudaFuncSetAttribute(yoshida_kernel,
                         cudaFuncAttributeMaxDynamicSharedMemorySize, (int)smem);
    yoshida_kernel<<<Bsz / TB, NT, smem>>>(x, v, force, U, W, Vw, steps, (float*)d_out);
}

// round 9
// speedup vs baseline: 1.1496x; 1.1496x over previous
#include <cuda_runtime.h>
#include <math.h>

#define Bsz 8192
#define Dd  1024
#define Rr  64
#define TB  8
#define NT  256

typedef unsigned long long ull;

// ---- Yoshida 4th-order coefficients ----
constexpr double kCbrt2 = 1.2599210498948731647672106072782;
constexpr double kW1 = 1.0 / (2.0 - kCbrt2);
constexpr double kW0 = -kCbrt2 * kW1;
constexpr double kDT = 0.01;

#define C1DT  ((float)((kW1 * 0.5) * kDT))
#define C2DT  ((float)(((kW0 + kW1) * 0.5) * kDT))
#define C4DT  C1DT
#define C41DT ((float)(kW1 * kDT))          // (C4 + C1) * dt
#define D1DT  ((float)(kW1 * kDT))
#define D2DT  ((float)(kW0 * kDT))

#define PLASTICITY    0.1f
#define SING_THRESH   10.0f
#define SING_STRENGTH 20.0f

// ---- packed f32x2 helpers (Blackwell) ----
__device__ __forceinline__ ull splat2(float x) {
    ull r; asm("mov.b64 %0, {%1, %1};" : "=l"(r) : "f"(x)); return r;
}
__device__ __forceinline__ ull fma2(ull a, ull b, ull c) {
    ull d; asm("fma.rn.f32x2 %0, %1, %2, %3;" : "=l"(d) : "l"(a), "l"(b), "l"(c)); return d;
}
__device__ __forceinline__ ull add2(ull a, ull b) {
    ull d; asm("add.rn.f32x2 %0, %1, %2;" : "=l"(d) : "l"(a), "l"(b)); return d;
}
__device__ __forceinline__ float2 unpk2(ull v) {
    float2 r; asm("mov.b64 {%0, %1}, %2;" : "=f"(r.x), "=f"(r.y) : "l"(v)); return r;
}

// Process one 4-d block: 8 rows x 4 r's, in two 4-row halves to limit registers.
__device__ __forceinline__ void block_fma(const float* __restrict__ sb, int d,
                                          const ulonglong2* u, ull* A)
{
    #pragma unroll
    for (int half = 0; half < 2; ++half) {
        float4 sv[4];
        #pragma unroll
        for (int j = 0; j < 4; ++j)
            sv[j] = *(const float4*)(sb + (half * 4 + j) * Dd + d);
        ull* Ah = A + half * 8;
        #pragma unroll
        for (int dd = 0; dd < 4; ++dd) {
            #pragma unroll
            for (int j = 0; j < 4; ++j) {
                const float f = (dd == 0) ? sv[j].x : (dd == 1) ? sv[j].y
                              : (dd == 2) ? sv[j].z : sv[j].w;
                const ull sp = splat2(f);
                Ah[j * 2 + 0] = fma2(sp, u[dd].x, Ah[j * 2 + 0]);
                Ah[j * 2 + 1] = fma2(sp, u[dd].y, Ah[j * 2 + 1]);
            }
        }
    }
}

// Rank pass with software-pipelined matrix LDG (one 4-d block ahead).
// All TB=8 rows of the state tile, 4 r's, over a 64-d slice.
__device__ __forceinline__ void rank_pass(const float* __restrict__ st,
                                          const float* __restrict__ mat,
                                          int rq, int d0, ull* A)
{
    #pragma unroll
    for (int c = 0; c < 16; ++c) A[c] = 0ull;
    const float* sb = st + d0;
    const float* mb = mat + (size_t)d0 * Rr + rq;

    ulonglong2 u[4];
    #pragma unroll
    for (int dd = 0; dd < 4; ++dd)
        u[dd] = *(const ulonglong2*)(mb + (size_t)dd * Rr);

    #pragma unroll 1
    for (int d = 0; d < 60; d += 4) {
        ulonglong2 un[4];
        #pragma unroll
        for (int dd = 0; dd < 4; ++dd)
            un[dd] = *(const ulonglong2*)(mb + (size_t)(d + 4 + dd) * Rr);
        block_fma(sb, d, u, A);
        #pragma unroll
        for (int dd = 0; dd < 4; ++dd) u[dd] = un[dd];
    }
    block_fma(sb, 60, u, A);
}

__global__ void __launch_bounds__(NT, 2)
yoshida_kernel(const float* __restrict__ x_in,
               const float* __restrict__ v_in,
               const float* __restrict__ force,
               const float* __restrict__ U,     // [D, R]
               const float* __restrict__ Wm,    // [R, D]
               const float* __restrict__ Vw,    // [D, R]
               const int*   __restrict__ steps_p,
               float* __restrict__ out)         // [x(B*D) ; v(B*D)]
{
    extern __shared__ float smem[];
    float* xs     = smem;                       // 8192 floats
    float* vs     = xs + TB * Dd;               // 8192
    float* qs     = vs + TB * Dd;               // 512  (qs[r*TB + row], sing folded)
    float* sing_s = qs + Rr * TB;               // 8
    ull*   part   = (ull*)(sing_s + TB);        // 4096 ull = 32KB (reused P/M)
    ull*   Pred   = part + 4096;                // 256 ull = 2KB (reduced P)

    const int tid  = threadIdx.x;
    const int row0 = blockIdx.x * TB;

    float4* sx4 = (float4*)xs;
    float4* sv4 = (float4*)vs;

    // ---- phase-2 mapping: 16 r-quads x 16 d-slices ----
    const int rqi = tid & 15;
    const int rq  = rqi * 4;
    const int ds  = tid >> 4;                   // 0..15
    // ---- reduce mapping: 16 components x 16 groups ----
    const int rc  = tid >> 4;                   // component 0..15
    const int rg  = tid & 15;                   // group (rqi) 0..15
    // ---- phase-3 mapping: 256 k-quads, all 8 rows ----
    const int k4  = tid * 4;
    // ---- drift mapping: warp per row ----
    const int drow = tid >> 5;                  // 0..7
    const int lane = tid & 31;

    // ---- load state tile ----
    {
        const float4* gx = (const float4*)(x_in + (size_t)row0 * Dd);
        const float4* gv = (const float4*)(v_in + (size_t)row0 * Dd);
        #pragma unroll
        for (int i = tid; i < TB * Dd / 4; i += NT) {
            sx4[i] = gx[i];
            sv4[i] = gv[i];
        }
    }

    const int nkicks = 3 * (*steps_p);

    for (int k = 0; k < nkicks; ++k) {
        const int sub = k - (k / 3) * 3;
        const float cdt = (k == 0) ? C1DT : (sub == 0) ? C41DT : C2DT;
        const float ddt = (sub == 1) ? D2DT : D1DT;

        __syncthreads();   // vs from prev kick visible; part free

        ull A[16];

        // ---- P-pass: P = v.U (pre-kick v; independent of drift) ----
        rank_pass(vs, U, rq, ds * 64, A);
        #pragma unroll
        for (int c = 0; c < 16; ++c)
            part[c * 256 + ds * 16 + rg] = A[c];

        // ---- drift + sing fused (warp per row, packed FMA2) ----
        {
            ulonglong2* xr = (ulonglong2*)(xs + drow * Dd);
            const ulonglong2* vr = (const ulonglong2*)(vs + drow * Dd);
            const ull cd2 = splat2(cdt);
            ull acc2 = 0ull;
            #pragma unroll
            for (int i = 0; i < 8; ++i) {
                ulonglong2 xv = xr[lane + 32 * i];
                const ulonglong2 vv = vr[lane + 32 * i];
                xv.x = fma2(cd2, vv.x, xv.x);
                xv.y = fma2(cd2, vv.y, xv.y);
                acc2 = fma2(xv.x, xv.x, acc2);
                acc2 = fma2(xv.y, xv.y, acc2);
                xr[lane + 32 * i] = xv;
            }
            const float2 a2 = unpk2(acc2);
            float acc = a2.x + a2.y;
            #pragma unroll
            for (int o = 16; o; o >>= 1)
                acc += __shfl_xor_sync(0xffffffffu, acc, o);
            if (lane == 0)
                sing_s[drow] = 1.0f + SING_STRENGTH * expf(-acc * (1.0f / SING_THRESH));
        }
        __syncthreads();

        // ---- P-reduce -> Pred ----
        {
            ull acc = part[rc * 256 + rg];
            #pragma unroll
            for (int p = 1; p < 16; ++p)
                acc = add2(acc, part[rc * 256 + p * 16 + rg]);
            Pred[rc * 16 + rg] = acc;
        }
        __syncthreads();   // part free for M-pass

        // ---- M-pass: M = x.Vw (drifted x) ----
        rank_pass(xs, Vw, rq, ds * 64, A);
        #pragma unroll
        for (int c = 0; c < 16; ++c)
            part[c * 256 + ds * 16 + rg] = A[c];
        __syncthreads();

        // ---- force prefetch for phase 3 (hides L2 latency under reduce) ----
        float4 fpre[8];
        #pragma unroll
        for (int j = 0; j < 8; ++j)
            fpre[j] = *(const float4*)(force + (size_t)(row0 + j) * Dd + k4);

        // ---- M-reduce + q epilogue (sing folded into q) ----
        {
            ull acc = part[rc * 256 + rg];
            #pragma unroll
            for (int p = 1; p < 16; ++p)
                acc = add2(acc, part[rc * 256 + p * 16 + rg]);
            const float2 m  = unpk2(acc);
            const float2 pv = unpk2(Pred[rc * 16 + rg]);
            const int rowq = rc >> 1;                 // 0..7
            const int rr   = rg * 4 + (rc & 1) * 2;
            const float sg = sing_s[rowq];
            qs[(rr + 0) * TB + rowq] = pv.x * pv.x * (1.0f + PLASTICITY * tanhf(m.x)) * sg;
            qs[(rr + 1) * TB + rowq] = pv.y * pv.y * (1.0f + PLASTICITY * tanhf(m.y)) * sg;
        }
        __syncthreads();

        // ---- phase 3: gamma = q.W (FMA2 over row-pairs, W prefetched);
        //      v += ddt*(force - gamma) ----
        {
            ull Acc[16];   // Acc[k*4 + rowpair]
            #pragma unroll
            for (int c = 0; c < 16; ++c) Acc[c] = 0ull;

            float4 w0 = *(const float4*)(Wm + k4);
            float4 w1 = *(const float4*)(Wm + Dd + k4);

            #pragma unroll 1
            for (int r = 0; r < Rr; r += 2) {
                float4 w0n, w1n;
                if (r < Rr - 2) {
                    w0n = *(const float4*)(Wm + (size_t)(r + 2) * Dd + k4);
                    w1n = *(const float4*)(Wm + (size_t)(r + 3) * Dd + k4);
                }
                const ulonglong2 qa0 = *(const ulonglong2*)(qs + r * TB);
                const ulonglong2 qb0 = *(const ulonglong2*)(qs + r * TB + 4);
                const ulonglong2 qa1 = *(const ulonglong2*)(qs + (r + 1) * TB);
                const ulonglong2 qb1 = *(const ulonglong2*)(qs + (r + 1) * TB + 4);
                {
                    const ull s0 = splat2(w0.x), s1 = splat2(w0.y);
                    const ull s2 = splat2(w0.z), s3 = splat2(w0.w);
                    Acc[0]  = fma2(qa0.x, s0, Acc[0]);  Acc[1]  = fma2(qa0.y, s0, Acc[1]);
                    Acc[2]  = fma2(qb0.x, s0, Acc[2]);  Acc[3]  = fma2(qb0.y, s0, Acc[3]);
                    Acc[4]  = fma2(qa0.x, s1, Acc[4]);  Acc[5]  = fma2(qa0.y, s1, Acc[5]);
                    Acc[6]  = fma2(qb0.x, s1, Acc[6]);  Acc[7]  = fma2(qb0.y, s1, Acc[7]);
                    Acc[8]  = fma2(qa0.x, s2, Acc[8]);  Acc[9]  = fma2(qa0.y, s2, Acc[9]);
                    Acc[10] = fma2(qb0.x, s2, Acc[10]); Acc[11] = fma2(qb0.y, s2, Acc[11]);
                    Acc[12] = fma2(qa0.x, s3, Acc[12]); Acc[13] = fma2(qa0.y, s3, Acc[13]);
                    Acc[14] = fma2(qb0.x, s3, Acc[14]); Acc[15] = fma2(qb0.y, s3, Acc[15]);
                }
                {
                    const ull s0 = splat2(w1.x), s1 = splat2(w1.y);
                    const ull s2 = splat2(w1.z), s3 = splat2(w1.w);
                    Acc[0]  = fma2(qa1.x, s0, Acc[0]);  Acc[1]  = fma2(qa1.y, s0, Acc[1]);
                    Acc[2]  = fma2(qb1.x, s0, Acc[2]);  Acc[3]  = fma2(qb1.y, s0, Acc[3]);
                    Acc[4]  = fma2(qa1.x, s1, Acc[4]);  Acc[5]  = fma2(qa1.y, s1, Acc[5]);
                    Acc[6]  = fma2(qb1.x, s1, Acc[6]);  Acc[7]  = fma2(qb1.y, s1, Acc[7]);
                    Acc[8]  = fma2(qa1.x, s2, Acc[8]);  Acc[9]  = fma2(qa1.y, s2, Acc[9]);
                    Acc[10] = fma2(qb1.x, s2, Acc[10]); Acc[11] = fma2(qb1.y, s2, Acc[11]);
                    Acc[12] = fma2(qa1.x, s3, Acc[12]); Acc[13] = fma2(qa1.y, s3, Acc[13]);
                    Acc[14] = fma2(qb1.x, s3, Acc[14]); Acc[15] = fma2(qb1.y, s3, Acc[15]);
                }
                w0 = w0n; w1 = w1n;
            }

            #pragma unroll
            for (int p = 0; p < 4; ++p) {
                const float2 g0 = unpk2(Acc[0 * 4 + p]);
                const float2 g1 = unpk2(Acc[1 * 4 + p]);
                const float2 g2 = unpk2(Acc[2 * 4 + p]);
                const float2 g3 = unpk2(Acc[3 * 4 + p]);
                const int re = 2 * p;
                {
                    const float4 f = fpre[re];
                    float4* vp = (float4*)(vs + re * Dd + k4);
                    float4 vv = *vp;
                    vv.x += ddt * (f.x - g0.x);
                    vv.y += ddt * (f.y - g1.x);
                    vv.z += ddt * (f.z - g2.x);
                    vv.w += ddt * (f.w - g3.x);
                    *vp = vv;
                }
                {
                    const int ro = re + 1;
                    const float4 f = fpre[ro];
                    float4* vp = (float4*)(vs + ro * Dd + k4);
                    float4 vv = *vp;
                    vv.x += ddt * (f.x - g0.y);
                    vv.y += ddt * (f.y - g1.y);
                    vv.z += ddt * (f.z - g2.y);
                    vv.w += ddt * (f.w - g3.y);
                    *vp = vv;
                }
            }
        }
    }

    // ---- store: out.x = xs + C4*dt*vs (final drift fused), out.v = vs ----
    __syncthreads();
    {
        const float fc = (nkicks > 0) ? C4DT : 0.0f;
        float4* ox = (float4*)(out + (size_t)row0 * Dd);
        float4* ov = (float4*)(out + (size_t)Bsz * Dd + (size_t)row0 * Dd);
        #pragma unroll
        for (int i = tid; i < TB * Dd / 4; i += NT) {
            const float4 xv = sx4[i];
            const float4 vv = sv4[i];
            float4 o;
            o.x = xv.x + fc * vv.x; o.y = xv.y + fc * vv.y;
            o.z = xv.z + fc * vv.z; o.w = xv.w + fc * vv.w;
            ox[i] = o;
            ov[i] = vv;
        }
    }
}

extern "C" void kernel_launch(void* const* d_in, const int* in_sizes, int n_in,
                              void* d_out, int out_size) {
    const float* x     = (const float*)d_in[0];
    const float* v     = (const float*)d_in[1];
    const float* force = (const float*)d_in[2];
    const float* U     = (const float*)d_in[3];
    const float* W     = (const float*)d_in[4];
    const float* Vw    = (const float*)d_in[5];
    const int*   steps = (const int*)d_in[6];

    const size_t smem = (size_t)(2 * TB * Dd + Rr * TB + TB) * sizeof(float)
                      + (size_t)(4096 + 256) * sizeof(ull);
    cudaFuncSetAttribute(yoshida_kernel,
                         cudaFuncAttributeMaxDynamicSharedMemorySize, (int)smem);
    yoshida_kernel<<<Bsz / TB, NT, smem>>>(x, v, force, U, W, Vw, steps, (float*)d_out);
}